// round 1
// baseline (speedup 1.0000x reference)
#include <cuda_runtime.h>
#include <math.h>

#define N_  4
#define C_  512
#define CT_ 512
#define L_  256
#define S_  4096
#define H_  16
#define D_  32

// Scratch for K/V projections (device globals: no allocs allowed)
__device__ float g_K[(size_t)N_ * C_ * L_];
__device__ float g_V[(size_t)N_ * C_ * L_];

// ---------------------------------------------------------------------------
// Kernel A: proj_v / proj_k = W @ token + b   (per batch, per {v,k})
// Standard smem-tiled GEMM: M=512 (out ch), N=256 (L), K=512 (CT)
// grid = (L/64, C/64, N*2), 256 threads, 4x4 per thread, k-chunk 32
// ---------------------------------------------------------------------------
extern "C" __global__ void __launch_bounds__(256)
proj_kv_kernel(const float* __restrict__ token,
               const float* __restrict__ Wv, const float* __restrict__ bv,
               const float* __restrict__ Wk, const float* __restrict__ bk)
{
    __shared__ float Wt[64][33];
    __shared__ float Tt[32][65];
    const int t  = threadIdx.x;
    const int tx = t & 15;        // l-group
    const int ty = t >> 4;        // o-group
    const int l0 = blockIdx.x * 64;
    const int o0 = blockIdx.y * 64;
    const int n     = blockIdx.z >> 1;
    const int which = blockIdx.z & 1;   // 0 -> V, 1 -> K
    const float* __restrict__ W    = which ? Wk : Wv;
    const float* __restrict__ bias = which ? bk : bv;
    float* out = which ? g_K : g_V;
    const float* tb = token + (size_t)n * CT_ * L_;

    float acc[4][4] = {};

    for (int kc = 0; kc < CT_; kc += 32) {
        #pragma unroll
        for (int i = t; i < 64 * 32; i += 256) {
            int o = i >> 5, c = i & 31;
            Wt[o][c] = W[(size_t)(o0 + o) * CT_ + kc + c];
        }
        #pragma unroll
        for (int i = t; i < 32 * 64; i += 256) {
            int c = i >> 6, l = i & 63;
            Tt[c][l] = tb[(size_t)(kc + c) * L_ + l0 + l];
        }
        __syncthreads();

        #pragma unroll 8
        for (int c = 0; c < 32; c++) {
            float a0 = Wt[ty * 4 + 0][c];
            float a1 = Wt[ty * 4 + 1][c];
            float a2 = Wt[ty * 4 + 2][c];
            float a3 = Wt[ty * 4 + 3][c];
            float b0 = Tt[c][tx * 4 + 0];
            float b1 = Tt[c][tx * 4 + 1];
            float b2 = Tt[c][tx * 4 + 2];
            float b3 = Tt[c][tx * 4 + 3];
            acc[0][0] += a0 * b0; acc[0][1] += a0 * b1; acc[0][2] += a0 * b2; acc[0][3] += a0 * b3;
            acc[1][0] += a1 * b0; acc[1][1] += a1 * b1; acc[1][2] += a1 * b2; acc[1][3] += a1 * b3;
            acc[2][0] += a2 * b0; acc[2][1] += a2 * b1; acc[2][2] += a2 * b2; acc[2][3] += a2 * b3;
            acc[3][0] += a3 * b0; acc[3][1] += a3 * b1; acc[3][2] += a3 * b2; acc[3][3] += a3 * b3;
        }
        __syncthreads();
    }

    #pragma unroll
    for (int i = 0; i < 4; i++) {
        int o = o0 + ty * 4 + i;
        float bb = bias[o];
        float4 v = make_float4(acc[i][0] + bb, acc[i][1] + bb,
                               acc[i][2] + bb, acc[i][3] + bb);
        *(float4*)&out[((size_t)n * C_ + o) * L_ + l0 + tx * 4] = v;
    }
}

// ---------------------------------------------------------------------------
// Kernel B: fused attention per (n, h, s-tile of 64)
//   Q-tile = Wq[h] @ feature_slice (scaled, +bq)  -> smem Qt[32][72] (d-major)
//   scores = Qt^T @ K      (8x8 per thread; warp ty owns rows, lanes own cols)
//   softmax over L=256 fully inside each warp (shfl reductions)
//   out    = P @ V^T       (shuffle-broadcast P, lane = output channel d)
//   residual add from smem feature tile, coalesced channel-major store
// smem layout (floats):
//   Wq:1024 | Qt:32*72 | K:32*260 | V:32*260 | F:32*65 | O:32*65
// ---------------------------------------------------------------------------
#define SM_WQ  0
#define SM_QT  1024
#define SM_K   (SM_QT + 32 * 72)
#define SM_V   (SM_K + 32 * 260)
#define SM_F   (SM_V + 32 * 260)
#define SM_O   (SM_F + 32 * 65)
#define SM_TOT (SM_O + 32 * 65)      // 24128 floats = 96512 bytes

extern "C" __global__ void __launch_bounds__(256, 2)
attn_kernel(const float* __restrict__ feature,
            const float* __restrict__ Wq, const float* __restrict__ bq,
            float* __restrict__ dout)
{
    extern __shared__ float sm[];
    const int t    = threadIdx.x;
    const int lane = t & 31;
    const int warp = t >> 5;
    const int s0 = blockIdx.x * 64;
    const int h  = blockIdx.y;
    const int n  = blockIdx.z;

    const float* fbase = feature + ((size_t)n * C_ + h * D_) * S_ + s0;
    const float* kbase = g_K + ((size_t)n * C_ + h * D_) * L_;
    const float* vbase = g_V + ((size_t)n * C_ + h * D_) * L_;

    // ---- loads ----
    #pragma unroll
    for (int i = t; i < 1024; i += 256)
        sm[SM_WQ + i] = Wq[h * 1024 + i];

    #pragma unroll
    for (int i = t; i < 512; i += 256) {            // feature tile 32x64
        int r = i >> 4, c4 = (i & 15) << 2;
        float4 v = *(const float4*)(fbase + (size_t)r * S_ + c4);
        float* d = &sm[SM_F + r * 65 + c4];
        d[0] = v.x; d[1] = v.y; d[2] = v.z; d[3] = v.w;
    }
    #pragma unroll
    for (int i = t; i < 2048; i += 256) {           // K tile 32x256
        int r = i >> 6, c4 = (i & 63) << 2;
        *(float4*)&sm[SM_K + r * 260 + c4] =
            *(const float4*)(kbase + (size_t)r * L_ + c4);
    }
    #pragma unroll
    for (int i = t; i < 2048; i += 256) {           // V tile 32x256
        int r = i >> 6, c4 = (i & 63) << 2;
        *(float4*)&sm[SM_V + r * 260 + c4] =
            *(const float4*)(vbase + (size_t)r * L_ + c4);
    }
    __syncthreads();

    // ---- Q tile: Qt[d][row] = (sum_i Wq[h][d][i]*F[i][row] + bq) * scale ----
    {
        const int row = t & 63;
        const int d0  = (t >> 6) << 3;
        float qa[8] = {};
        #pragma unroll 8
        for (int i = 0; i < 32; i++) {
            float f = sm[SM_F + i * 65 + row];
            #pragma unroll
            for (int dd = 0; dd < 8; dd++)
                qa[dd] += sm[SM_WQ + (d0 + dd) * 32 + i] * f;
        }
        const float scale = 0.17677669529663687f;   // 1/sqrt(32)
        #pragma unroll
        for (int dd = 0; dd < 8; dd++)
            sm[SM_QT + (d0 + dd) * 72 + row] = (qa[dd] + bq[h * D_ + d0 + dd]) * scale;
    }
    __syncthreads();

    // ---- GEMM1: p[r][c] = scores for rows warp*8+r, cols lane*8+c ----
    float p[8][8] = {};
    {
        const int r0 = warp * 8, c0 = lane * 8;
        #pragma unroll 4
        for (int d = 0; d < 32; d++) {
            float4 qa = *(const float4*)&sm[SM_QT + d * 72 + r0];
            float4 qb = *(const float4*)&sm[SM_QT + d * 72 + r0 + 4];
            float4 ka = *(const float4*)&sm[SM_K + d * 260 + c0];
            float4 kb = *(const float4*)&sm[SM_K + d * 260 + c0 + 4];
            float q[8] = {qa.x, qa.y, qa.z, qa.w, qb.x, qb.y, qb.z, qb.w};
            float k[8] = {ka.x, ka.y, ka.z, ka.w, kb.x, kb.y, kb.z, kb.w};
            #pragma unroll
            for (int r = 0; r < 8; r++)
                #pragma unroll
                for (int c = 0; c < 8; c++)
                    p[r][c] += q[r] * k[c];
        }
    }

    // ---- softmax over L within each warp (each warp owns 8 full rows) ----
    float rinv[8];
    #pragma unroll
    for (int r = 0; r < 8; r++) {
        float m = p[r][0];
        #pragma unroll
        for (int c = 1; c < 8; c++) m = fmaxf(m, p[r][c]);
        #pragma unroll
        for (int o = 16; o > 0; o >>= 1)
            m = fmaxf(m, __shfl_xor_sync(0xffffffffu, m, o));
        float s = 0.f;
        #pragma unroll
        for (int c = 0; c < 8; c++) {
            float e = __expf(p[r][c] - m);
            p[r][c] = e;
            s += e;
        }
        #pragma unroll
        for (int o = 16; o > 0; o >>= 1)
            s += __shfl_xor_sync(0xffffffffu, s, o);
        rinv[r] = __fdividef(1.0f, s);
    }

    // ---- GEMM2: out[row][d=lane] = sum_l P[row][l] * V[d][l] ----
    float acc2[8] = {};
    {
        const float* vrow = &sm[SM_V + lane * 260];
        #pragma unroll 1
        for (int src = 0; src < 32; src++) {
            float4 va = *(const float4*)(vrow + src * 8);
            float4 vb = *(const float4*)(vrow + src * 8 + 4);
            float v[8] = {va.x, va.y, va.z, va.w, vb.x, vb.y, vb.z, vb.w};
            #pragma unroll
            for (int r = 0; r < 8; r++) {
                #pragma unroll
                for (int j = 0; j < 8; j++) {
                    float pb = __shfl_sync(0xffffffffu, p[r][j], src);
                    acc2[r] += pb * v[j];
                }
            }
        }
    }

    // ---- epilogue: normalize + residual into smem (transposed), store ----
    #pragma unroll
    for (int r = 0; r < 8; r++) {
        int row = warp * 8 + r;
        sm[SM_O + lane * 65 + row] = acc2[r] * rinv[r] + sm[SM_F + lane * 65 + row];
    }
    __syncthreads();

    float* obase = dout + ((size_t)n * C_ + h * D_) * S_ + s0;
    #pragma unroll
    for (int i = t; i < 512; i += 256) {
        int d = i >> 4, c4 = (i & 15) << 2;
        float4 v;
        v.x = sm[SM_O + d * 65 + c4 + 0];
        v.y = sm[SM_O + d * 65 + c4 + 1];
        v.z = sm[SM_O + d * 65 + c4 + 2];
        v.w = sm[SM_O + d * 65 + c4 + 3];
        *(float4*)(obase + (size_t)d * S_ + c4) = v;
    }
}

// ---------------------------------------------------------------------------
extern "C" void kernel_launch(void* const* d_in, const int* in_sizes, int n_in,
                              void* d_out, int out_size)
{
    const float* feature = (const float*)d_in[0];
    const float* token   = (const float*)d_in[1];
    const float* Wv      = (const float*)d_in[2];
    const float* bv      = (const float*)d_in[3];
    const float* Wk      = (const float*)d_in[4];
    const float* bk      = (const float*)d_in[5];
    const float* Wq      = (const float*)d_in[6];
    const float* bq      = (const float*)d_in[7];
    float* out = (float*)d_out;

    cudaFuncSetAttribute(attn_kernel,
                         cudaFuncAttributeMaxDynamicSharedMemorySize,
                         SM_TOT * (int)sizeof(float));

    proj_kv_kernel<<<dim3(L_ / 64, C_ / 64, N_ * 2), 256>>>(token, Wv, bv, Wk, bk);
    attn_kernel<<<dim3(S_ / 64, H_, N_), 256, SM_TOT * sizeof(float)>>>(feature, Wq, bq, out);
}

// round 2
// speedup vs baseline: 1.0015x; 1.0015x over previous
#include <cuda_runtime.h>
#include <math.h>

#define N_  4
#define C_  512
#define CT_ 512
#define L_  256
#define S_  4096
#define H_  16
#define D_  32

// Scratch for K/V projections (device globals: no allocs allowed)
__device__ float g_K[(size_t)N_ * C_ * L_];
__device__ float g_V[(size_t)N_ * C_ * L_];

// ---------------------------------------------------------------------------
// Kernel A: proj_v / proj_k = W @ token + b   (per batch, per {v,k})
// Standard smem-tiled GEMM: M=512 (out ch), N=256 (L), K=512 (CT)
// grid = (L/64, C/64, N*2), 256 threads, 4x4 per thread, k-chunk 32
// ---------------------------------------------------------------------------
extern "C" __global__ void __launch_bounds__(256)
proj_kv_kernel(const float* __restrict__ token,
               const float* __restrict__ Wv, const float* __restrict__ bv,
               const float* __restrict__ Wk, const float* __restrict__ bk)
{
    __shared__ float Wt[64][33];
    __shared__ float Tt[32][65];
    const int t  = threadIdx.x;
    const int tx = t & 15;        // l-group
    const int ty = t >> 4;        // o-group
    const int l0 = blockIdx.x * 64;
    const int o0 = blockIdx.y * 64;
    const int n     = blockIdx.z >> 1;
    const int which = blockIdx.z & 1;   // 0 -> V, 1 -> K
    const float* __restrict__ W    = which ? Wk : Wv;
    const float* __restrict__ bias = which ? bk : bv;
    float* out = which ? g_K : g_V;
    const float* tb = token + (size_t)n * CT_ * L_;

    float acc[4][4] = {};

    for (int kc = 0; kc < CT_; kc += 32) {
        #pragma unroll
        for (int i = t; i < 64 * 32; i += 256) {
            int o = i >> 5, c = i & 31;
            Wt[o][c] = W[(size_t)(o0 + o) * CT_ + kc + c];
        }
        #pragma unroll
        for (int i = t; i < 32 * 64; i += 256) {
            int c = i >> 6, l = i & 63;
            Tt[c][l] = tb[(size_t)(kc + c) * L_ + l0 + l];
        }
        __syncthreads();

        #pragma unroll 8
        for (int c = 0; c < 32; c++) {
            float a0 = Wt[ty * 4 + 0][c];
            float a1 = Wt[ty * 4 + 1][c];
            float a2 = Wt[ty * 4 + 2][c];
            float a3 = Wt[ty * 4 + 3][c];
            float b0 = Tt[c][tx * 4 + 0];
            float b1 = Tt[c][tx * 4 + 1];
            float b2 = Tt[c][tx * 4 + 2];
            float b3 = Tt[c][tx * 4 + 3];
            acc[0][0] += a0 * b0; acc[0][1] += a0 * b1; acc[0][2] += a0 * b2; acc[0][3] += a0 * b3;
            acc[1][0] += a1 * b0; acc[1][1] += a1 * b1; acc[1][2] += a1 * b2; acc[1][3] += a1 * b3;
            acc[2][0] += a2 * b0; acc[2][1] += a2 * b1; acc[2][2] += a2 * b2; acc[2][3] += a2 * b3;
            acc[3][0] += a3 * b0; acc[3][1] += a3 * b1; acc[3][2] += a3 * b2; acc[3][3] += a3 * b3;
        }
        __syncthreads();
    }

    #pragma unroll
    for (int i = 0; i < 4; i++) {
        int o = o0 + ty * 4 + i;
        float bb = bias[o];
        float4 v = make_float4(acc[i][0] + bb, acc[i][1] + bb,
                               acc[i][2] + bb, acc[i][3] + bb);
        *(float4*)&out[((size_t)n * C_ + o) * L_ + l0 + tx * 4] = v;
    }
}

// ---------------------------------------------------------------------------
// Kernel B: fused attention per (n, h, s-tile of 64)
//   Q-tile = Wq[h] @ feature_slice (scaled, +bq)  -> smem Qt[32][72] (d-major)
//   scores = Qt^T @ K      (8x8 per thread; warp ty owns rows, lanes own cols)
//   softmax over L=256 fully inside each warp (shfl reductions)
//   out    = P @ V^T       (shuffle-broadcast P, lane = output channel d)
//   residual add from smem feature tile, coalesced channel-major store
// smem layout (floats):
//   Wq:1024 | Qt:32*72 | K:32*260 | V:32*260 | F:32*65 | O:32*65
// ---------------------------------------------------------------------------
#define SM_WQ  0
#define SM_QT  1024
#define SM_K   (SM_QT + 32 * 72)
#define SM_V   (SM_K + 32 * 260)
#define SM_F   (SM_V + 32 * 260)
#define SM_O   (SM_F + 32 * 65)
#define SM_TOT (SM_O + 32 * 65)      // 24128 floats = 96512 bytes

extern "C" __global__ void __launch_bounds__(256, 2)
attn_kernel(const float* __restrict__ feature,
            const float* __restrict__ Wq, const float* __restrict__ bq,
            float* __restrict__ dout)
{
    extern __shared__ float sm[];
    const int t    = threadIdx.x;
    const int lane = t & 31;
    const int warp = t >> 5;
    const int s0 = blockIdx.x * 64;
    const int h  = blockIdx.y;
    const int n  = blockIdx.z;

    const float* fbase = feature + ((size_t)n * C_ + h * D_) * S_ + s0;
    const float* kbase = g_K + ((size_t)n * C_ + h * D_) * L_;
    const float* vbase = g_V + ((size_t)n * C_ + h * D_) * L_;

    // ---- loads ----
    #pragma unroll
    for (int i = t; i < 1024; i += 256)
        sm[SM_WQ + i] = Wq[h * 1024 + i];

    #pragma unroll
    for (int i = t; i < 512; i += 256) {            // feature tile 32x64
        int r = i >> 4, c4 = (i & 15) << 2;
        float4 v = *(const float4*)(fbase + (size_t)r * S_ + c4);
        float* d = &sm[SM_F + r * 65 + c4];
        d[0] = v.x; d[1] = v.y; d[2] = v.z; d[3] = v.w;
    }
    #pragma unroll
    for (int i = t; i < 2048; i += 256) {           // K tile 32x256
        int r = i >> 6, c4 = (i & 63) << 2;
        *(float4*)&sm[SM_K + r * 260 + c4] =
            *(const float4*)(kbase + (size_t)r * L_ + c4);
    }
    #pragma unroll
    for (int i = t; i < 2048; i += 256) {           // V tile 32x256
        int r = i >> 6, c4 = (i & 63) << 2;
        *(float4*)&sm[SM_V + r * 260 + c4] =
            *(const float4*)(vbase + (size_t)r * L_ + c4);
    }
    __syncthreads();

    // ---- Q tile: Qt[d][row] = (sum_i Wq[h][d][i]*F[i][row] + bq) * scale ----
    {
        const int row = t & 63;
        const int d0  = (t >> 6) << 3;
        float qa[8] = {};
        #pragma unroll 8
        for (int i = 0; i < 32; i++) {
            float f = sm[SM_F + i * 65 + row];
            #pragma unroll
            for (int dd = 0; dd < 8; dd++)
                qa[dd] += sm[SM_WQ + (d0 + dd) * 32 + i] * f;
        }
        const float scale = 0.17677669529663687f;   // 1/sqrt(32)
        #pragma unroll
        for (int dd = 0; dd < 8; dd++)
            sm[SM_QT + (d0 + dd) * 72 + row] = (qa[dd] + bq[h * D_ + d0 + dd]) * scale;
    }
    __syncthreads();

    // ---- GEMM1: p[r][c] = scores for rows warp*8+r, cols lane*8+c ----
    float p[8][8] = {};
    {
        const int r0 = warp * 8, c0 = lane * 8;
        #pragma unroll 4
        for (int d = 0; d < 32; d++) {
            float4 qa = *(const float4*)&sm[SM_QT + d * 72 + r0];
            float4 qb = *(const float4*)&sm[SM_QT + d * 72 + r0 + 4];
            float4 ka = *(const float4*)&sm[SM_K + d * 260 + c0];
            float4 kb = *(const float4*)&sm[SM_K + d * 260 + c0 + 4];
            float q[8] = {qa.x, qa.y, qa.z, qa.w, qb.x, qb.y, qb.z, qb.w};
            float k[8] = {ka.x, ka.y, ka.z, ka.w, kb.x, kb.y, kb.z, kb.w};
            #pragma unroll
            for (int r = 0; r < 8; r++)
                #pragma unroll
                for (int c = 0; c < 8; c++)
                    p[r][c] += q[r] * k[c];
        }
    }

    // ---- softmax over L within each warp (each warp owns 8 full rows) ----
    float rinv[8];
    #pragma unroll
    for (int r = 0; r < 8; r++) {
        float m = p[r][0];
        #pragma unroll
        for (int c = 1; c < 8; c++) m = fmaxf(m, p[r][c]);
        #pragma unroll
        for (int o = 16; o > 0; o >>= 1)
            m = fmaxf(m, __shfl_xor_sync(0xffffffffu, m, o));
        float s = 0.f;
        #pragma unroll
        for (int c = 0; c < 8; c++) {
            float e = __expf(p[r][c] - m);
            p[r][c] = e;
            s += e;
        }
        #pragma unroll
        for (int o = 16; o > 0; o >>= 1)
            s += __shfl_xor_sync(0xffffffffu, s, o);
        rinv[r] = __fdividef(1.0f, s);
    }

    // ---- GEMM2: out[row][d=lane] = sum_l P[row][l] * V[d][l] ----
    float acc2[8] = {};
    {
        const float* vrow = &sm[SM_V + lane * 260];
        #pragma unroll 1
        for (int src = 0; src < 32; src++) {
            float4 va = *(const float4*)(vrow + src * 8);
            float4 vb = *(const float4*)(vrow + src * 8 + 4);
            float v[8] = {va.x, va.y, va.z, va.w, vb.x, vb.y, vb.z, vb.w};
            #pragma unroll
            for (int r = 0; r < 8; r++) {
                #pragma unroll
                for (int j = 0; j < 8; j++) {
                    float pb = __shfl_sync(0xffffffffu, p[r][j], src);
                    acc2[r] += pb * v[j];
                }
            }
        }
    }

    // ---- epilogue: normalize + residual into smem (transposed), store ----
    #pragma unroll
    for (int r = 0; r < 8; r++) {
        int row = warp * 8 + r;
        sm[SM_O + lane * 65 + row] = acc2[r] * rinv[r] + sm[SM_F + lane * 65 + row];
    }
    __syncthreads();

    float* obase = dout + ((size_t)n * C_ + h * D_) * S_ + s0;
    #pragma unroll
    for (int i = t; i < 512; i += 256) {
        int d = i >> 4, c4 = (i & 15) << 2;
        float4 v;
        v.x = sm[SM_O + d * 65 + c4 + 0];
        v.y = sm[SM_O + d * 65 + c4 + 1];
        v.z = sm[SM_O + d * 65 + c4 + 2];
        v.w = sm[SM_O + d * 65 + c4 + 3];
        *(float4*)(obase + (size_t)d * S_ + c4) = v;
    }
}

// ---------------------------------------------------------------------------
extern "C" void kernel_launch(void* const* d_in, const int* in_sizes, int n_in,
                              void* d_out, int out_size)
{
    const float* feature = (const float*)d_in[0];
    const float* token   = (const float*)d_in[1];
    const float* Wv      = (const float*)d_in[2];
    const float* bv      = (const float*)d_in[3];
    const float* Wk      = (const float*)d_in[4];
    const float* bk      = (const float*)d_in[5];
    const float* Wq      = (const float*)d_in[6];
    const float* bq      = (const float*)d_in[7];
    float* out = (float*)d_out;

    cudaFuncSetAttribute(attn_kernel,
                         cudaFuncAttributeMaxDynamicSharedMemorySize,
                         SM_TOT * (int)sizeof(float));

    proj_kv_kernel<<<dim3(L_ / 64, C_ / 64, N_ * 2), 256>>>(token, Wv, bv, Wk, bk);
    attn_kernel<<<dim3(S_ / 64, H_, N_), 256, SM_TOT * sizeof(float)>>>(feature, Wq, bq, out);
}

// round 4
// speedup vs baseline: 2.9705x; 2.9661x over previous
#include <cuda_runtime.h>
#include <cuda_bf16.h>
#include <cstdint>
#include <math.h>

#define N_  4
#define C_  512
#define CT_ 512
#define L_  256
#define S_  4096
#define H_  16
#define D_  32

__device__ float g_K[(size_t)N_ * C_ * L_];
__device__ float g_V[(size_t)N_ * C_ * L_];

// ---------------- helpers ----------------
__device__ __forceinline__ float ex2f(float x) {
    float r; asm("ex2.approx.f32 %0, %1;" : "=f"(r) : "f"(x)); return r;
}
// pack two floats to bf16x2: low half = lo, high half = hi
__device__ __forceinline__ uint32_t pack_bf2(float lo, float hi) {
    uint32_t r; asm("cvt.rn.bf16x2.f32 %0, %1, %2;" : "=r"(r) : "f"(hi), "f"(lo)); return r;
}
__device__ __forceinline__ float bf_lo(uint32_t r) { return __uint_as_float(r << 16); }
__device__ __forceinline__ float bf_hi(uint32_t r) { return __uint_as_float(r & 0xFFFF0000u); }
// split x -> (hi_pack, lo_pack) for a pair
__device__ __forceinline__ void split2(float x0, float x1, uint32_t& hp, uint32_t& lp) {
    hp = pack_bf2(x0, x1);
    lp = pack_bf2(x0 - bf_lo(hp), x1 - bf_hi(hp));
}
// m16n8k16 bf16 MMA, C += A*B
__device__ __forceinline__ void mma16816(float* c, const uint32_t* a, uint32_t b0, uint32_t b1) {
    asm volatile("mma.sync.aligned.m16n8k16.row.col.f32.bf16.bf16.f32 "
                 "{%0,%1,%2,%3}, {%4,%5,%6,%7}, {%8,%9}, {%0,%1,%2,%3};"
                 : "+f"(c[0]), "+f"(c[1]), "+f"(c[2]), "+f"(c[3])
                 : "r"(a[0]), "r"(a[1]), "r"(a[2]), "r"(a[3]), "r"(b0), "r"(b1));
}

// ---------------------------------------------------------------------------
// Kernel A: K/V projections (unchanged from round 1; ~25us)
// ---------------------------------------------------------------------------
extern "C" __global__ void __launch_bounds__(256)
proj_kv_kernel(const float* __restrict__ token,
               const float* __restrict__ Wv, const float* __restrict__ bv,
               const float* __restrict__ Wk, const float* __restrict__ bk)
{
    __shared__ float Wt[64][33];
    __shared__ float Tt[32][65];
    const int t  = threadIdx.x;
    const int tx = t & 15, ty = t >> 4;
    const int l0 = blockIdx.x * 64, o0 = blockIdx.y * 64;
    const int n = blockIdx.z >> 1, which = blockIdx.z & 1;
    const float* __restrict__ W    = which ? Wk : Wv;
    const float* __restrict__ bias = which ? bk : bv;
    float* out = which ? g_K : g_V;
    const float* tb = token + (size_t)n * CT_ * L_;

    float acc[4][4] = {};
    for (int kc = 0; kc < CT_; kc += 32) {
        #pragma unroll
        for (int i = t; i < 64 * 32; i += 256) {
            int o = i >> 5, c = i & 31;
            Wt[o][c] = W[(size_t)(o0 + o) * CT_ + kc + c];
        }
        #pragma unroll
        for (int i = t; i < 32 * 64; i += 256) {
            int c = i >> 6, l = i & 63;
            Tt[c][l] = tb[(size_t)(kc + c) * L_ + l0 + l];
        }
        __syncthreads();
        #pragma unroll 8
        for (int c = 0; c < 32; c++) {
            float a0 = Wt[ty*4+0][c], a1 = Wt[ty*4+1][c], a2 = Wt[ty*4+2][c], a3 = Wt[ty*4+3][c];
            float b0 = Tt[c][tx*4+0], b1 = Tt[c][tx*4+1], b2 = Tt[c][tx*4+2], b3 = Tt[c][tx*4+3];
            acc[0][0]+=a0*b0; acc[0][1]+=a0*b1; acc[0][2]+=a0*b2; acc[0][3]+=a0*b3;
            acc[1][0]+=a1*b0; acc[1][1]+=a1*b1; acc[1][2]+=a1*b2; acc[1][3]+=a1*b3;
            acc[2][0]+=a2*b0; acc[2][1]+=a2*b1; acc[2][2]+=a2*b2; acc[2][3]+=a2*b3;
            acc[3][0]+=a3*b0; acc[3][1]+=a3*b1; acc[3][2]+=a3*b2; acc[3][3]+=a3*b3;
        }
        __syncthreads();
    }
    #pragma unroll
    for (int i = 0; i < 4; i++) {
        int o = o0 + ty * 4 + i;
        float bb = bias[o];
        float4 v = make_float4(acc[i][0]+bb, acc[i][1]+bb, acc[i][2]+bb, acc[i][3]+bb);
        *(float4*)&out[((size_t)n * C_ + o) * L_ + l0 + tx * 4] = v;
    }
}

// ---------------------------------------------------------------------------
// Kernel B: mma.sync bf16-split attention. Block = 128 s-rows x 1 head.
// 8 warps; warp w owns rows [w*16, w*16+16).
// smem (floats, strides chosen for conflict-free fragment LDS):
//   F  [32][132]  fp32 feature tile (residual + Q proj input)
//   WQ [1024]
//   QH/QL [16 pairs][136]  bf16x2 Q (d-pair major), stride%32==8
//   KH/KL [16 pairs][264]  bf16x2 K (d-pair major, l cols), stride%32==8
//   VH/VL [32 d][132]      bf16x2 V (l-pair cols), stride%32==4
//   O reuses QH/QL region after a barrier.
// ---------------------------------------------------------------------------
#define SB_F    0
#define SB_WQ   16896
#define SB_QHI  20992
#define SB_QLO  29696
#define SB_KHI  38400
#define SB_KLO  55296
#define SB_VHI  72192
#define SB_VLO  89088
#define SB_TOT  105984

extern "C" __global__ void __launch_bounds__(256, 2)
attn_mma_kernel(const float* __restrict__ feature,
                const float* __restrict__ Wq, const float* __restrict__ bq,
                float* __restrict__ dout)
{
    extern __shared__ char smem[];
    float*    smf = (float*)smem;
    uint32_t* QH  = (uint32_t*)(smem + SB_QHI);
    uint32_t* QL  = (uint32_t*)(smem + SB_QLO);
    uint32_t* KH  = (uint32_t*)(smem + SB_KHI);
    uint32_t* KL  = (uint32_t*)(smem + SB_KLO);
    uint32_t* VH  = (uint32_t*)(smem + SB_VHI);
    uint32_t* VL  = (uint32_t*)(smem + SB_VLO);
    float*    Osm = (float*)(smem + SB_QHI);      // reuse after barrier

    const int t    = threadIdx.x;
    const int lane = t & 31;
    const int wid  = t >> 5;
    const int g    = lane >> 2;      // row group 0..7
    const int tig  = lane & 3;       // thread in group
    const int s0 = blockIdx.x * 128;
    const int h  = blockIdx.y;
    const int n  = blockIdx.z;

    // ---------------- stage tiles ----------------
    const float* fb = feature + ((size_t)(n * C_ + h * D_)) * S_ + s0;
    #pragma unroll
    for (int i = t; i < 1024; i += 256) {                 // F: 32ch x 128s
        int row = i >> 5, c4 = (i & 31) << 2;
        *(float4*)&smf[row * 132 + c4] = *(const float4*)(fb + (size_t)row * S_ + c4);
    }
    #pragma unroll
    for (int i = t; i < 1024; i += 256)
        smf[SB_WQ/4 + i] = Wq[h * 1024 + i];

    const float* kb = g_K + ((size_t)(n * C_ + h * D_)) * L_;
    #pragma unroll 4
    for (int i = t; i < 4096; i += 256) {                 // K pairs: [p][l]
        int p = i >> 8, l = i & 255;
        float v0 = kb[(size_t)(2*p)   * L_ + l];
        float v1 = kb[(size_t)(2*p+1) * L_ + l];
        uint32_t hp, lp; split2(v0, v1, hp, lp);
        KH[p * 264 + l] = hp;
        KL[p * 264 + l] = lp;
    }
    const float* vb = g_V + ((size_t)(n * C_ + h * D_)) * L_;
    #pragma unroll 4
    for (int i = t; i < 4096; i += 256) {                 // V: [d][l-pair]
        int d = i >> 7, lp2 = i & 127;
        float2 v = *(const float2*)(vb + (size_t)d * L_ + lp2 * 2);
        uint32_t hp, lp; split2(v.x, v.y, hp, lp);
        VH[d * 132 + lp2] = hp;
        VL[d * 132 + lp2] = lp;
    }
    __syncthreads();

    // ---------------- Q projection -> bf16 split in smem ----------------
    {
        const int row = t & 127;
        const int d0  = (t >> 7) << 4;                    // 0 or 16
        float acc[16] = {};
        #pragma unroll 8
        for (int i = 0; i < 32; i++) {
            float f = smf[i * 132 + row];
            #pragma unroll
            for (int dd = 0; dd < 16; dd++)
                acc[dd] += smf[SB_WQ/4 + (d0 + dd) * 32 + i] * f;
        }
        // scale = (1/sqrt(32)) * log2(e): fold exp->ex2 conversion in here
        const float scale = 0.2550354839f;
        #pragma unroll
        for (int j = 0; j < 8; j++) {
            int d = d0 + 2 * j;
            float q0 = (acc[2*j]   + bq[h*D_ + d])   * scale;
            float q1 = (acc[2*j+1] + bq[h*D_ + d+1]) * scale;
            uint32_t hp, lp; split2(q0, q1, hp, lp);
            QH[(d >> 1) * 136 + row] = hp;
            QL[(d >> 1) * 136 + row] = lp;
        }
    }
    __syncthreads();

    // ---------------- load Q A-fragments (then Q smem is dead) ----------
    const int r0 = wid * 16;
    uint32_t aH[2][4], aL[2][4];
    #pragma unroll
    for (int ks = 0; ks < 2; ks++) {
        int p0 = ks * 8 + tig;
        aH[ks][0] = QH[p0 * 136 + r0 + g];
        aH[ks][1] = QH[p0 * 136 + r0 + g + 8];
        aH[ks][2] = QH[(p0 + 4) * 136 + r0 + g];
        aH[ks][3] = QH[(p0 + 4) * 136 + r0 + g + 8];
        aL[ks][0] = QL[p0 * 136 + r0 + g];
        aL[ks][1] = QL[p0 * 136 + r0 + g + 8];
        aL[ks][2] = QL[(p0 + 4) * 136 + r0 + g];
        aL[ks][3] = QL[(p0 + 4) * 136 + r0 + g + 8];
    }
    __syncthreads();   // all warps done reading Q before O overwrites it

    // ---------------- fused scores -> exp -> PV loop --------------------
    float o[4][4] = {};
    float sum0 = 0.f, sum1 = 0.f;           // row g+r0 and g+8+r0 partial sums

    #pragma unroll 1
    for (int cb = 0; cb < 8; cb++) {
        // ---- GEMM1: 4 n-tiles of 8 cols ----
        float c[4][4] = {};
        #pragma unroll
        for (int nt = 0; nt < 4; nt++) {
            const int lcol = cb * 32 + nt * 8 + g;
            #pragma unroll
            for (int ks = 0; ks < 2; ks++) {
                const int kp = (ks * 8 + tig) * 264 + lcol;
                uint32_t bh0 = KH[kp],          bh1 = KH[kp + 4 * 264];
                uint32_t bl0 = KL[kp],          bl1 = KL[kp + 4 * 264];
                mma16816(c[nt], aH[ks], bh0, bh1);
                mma16816(c[nt], aH[ks], bl0, bl1);
                mma16816(c[nt], aL[ks], bh0, bh1);
            }
        }
        // ---- exp (ex2; log2e already folded into Q scale) + row sums ----
        float e[4][4];
        #pragma unroll
        for (int nt = 0; nt < 4; nt++) {
            e[nt][0] = ex2f(c[nt][0]);
            e[nt][1] = ex2f(c[nt][1]);
            e[nt][2] = ex2f(c[nt][2]);
            e[nt][3] = ex2f(c[nt][3]);
            sum0 += e[nt][0] + e[nt][1];
            sum1 += e[nt][2] + e[nt][3];
        }
        // ---- P fragments: C-frag pairs -> A-frag regs (no shuffles) ----
        uint32_t pH[2][4], pL[2][4];
        #pragma unroll
        for (int kc = 0; kc < 2; kc++) {
            int t0 = 2 * kc, t1 = 2 * kc + 1;
            split2(e[t0][0], e[t0][1], pH[kc][0], pL[kc][0]);
            split2(e[t0][2], e[t0][3], pH[kc][1], pL[kc][1]);
            split2(e[t1][0], e[t1][1], pH[kc][2], pL[kc][2]);
            split2(e[t1][2], e[t1][3], pH[kc][3], pL[kc][3]);
        }
        // ---- GEMM2: accumulate P @ V^T into out ----
        #pragma unroll
        for (int dt = 0; dt < 4; dt++) {
            const int vrow = (dt * 8 + g) * 132;
            #pragma unroll
            for (int kc = 0; kc < 2; kc++) {
                const int vp = vrow + cb * 16 + kc * 8 + tig;
                uint32_t vh0 = VH[vp], vh1 = VH[vp + 4];
                uint32_t vl0 = VL[vp], vl1 = VL[vp + 4];
                mma16816(o[dt], pH[kc], vh0, vh1);
                mma16816(o[dt], pH[kc], vl0, vl1);
                mma16816(o[dt], pL[kc], vh0, vh1);
            }
        }
    }

    // ---------------- epilogue ----------------
    // full row sums within each quad (4 lanes cover a row's 256 cols)
    sum0 += __shfl_xor_sync(0xffffffffu, sum0, 1);
    sum0 += __shfl_xor_sync(0xffffffffu, sum0, 2);
    sum1 += __shfl_xor_sync(0xffffffffu, sum1, 1);
    sum1 += __shfl_xor_sync(0xffffffffu, sum1, 2);
    float rinv0 = __fdividef(1.0f, sum0);
    float rinv1 = __fdividef(1.0f, sum1);

    #pragma unroll
    for (int dt = 0; dt < 4; dt++) {
        int d = dt * 8 + 2 * tig;
        Osm[d * 132 + r0 + g]           = o[dt][0] * rinv0;
        Osm[(d + 1) * 132 + r0 + g]     = o[dt][1] * rinv0;
        Osm[d * 132 + r0 + g + 8]       = o[dt][2] * rinv1;
        Osm[(d + 1) * 132 + r0 + g + 8] = o[dt][3] * rinv1;
    }
    __syncthreads();

    // residual add + coalesced store (32 d-rows x 128 s-cols)
    float* ob = dout + ((size_t)(n * C_ + h * D_)) * S_ + s0;
    #pragma unroll
    for (int j = 0; j < 4; j++) {
        int i = t + j * 256;
        int d = i >> 5, c4 = (i & 31) << 2;
        float4 ov = *(float4*)&Osm[d * 132 + c4];
        float4 fv = *(float4*)&smf[d * 132 + c4];
        ov.x += fv.x; ov.y += fv.y; ov.z += fv.z; ov.w += fv.w;
        *(float4*)(ob + (size_t)d * S_ + c4) = ov;
    }
}

// ---------------------------------------------------------------------------
extern "C" void kernel_launch(void* const* d_in, const int* in_sizes, int n_in,
                              void* d_out, int out_size)
{
    const float* feature = (const float*)d_in[0];
    const float* token   = (const float*)d_in[1];
    const float* Wv      = (const float*)d_in[2];
    const float* bv      = (const float*)d_in[3];
    const float* Wk      = (const float*)d_in[4];
    const float* bk      = (const float*)d_in[5];
    const float* Wq      = (const float*)d_in[6];
    const float* bq      = (const float*)d_in[7];
    float* out = (float*)d_out;

    cudaFuncSetAttribute(attn_mma_kernel,
                         cudaFuncAttributeMaxDynamicSharedMemorySize, SB_TOT);

    proj_kv_kernel<<<dim3(L_/64, C_/64, N_*2), 256>>>(token, Wv, bv, Wk, bk);
    attn_mma_kernel<<<dim3(S_/128, H_, N_), 256, SB_TOT>>>(feature, Wq, bq, out);
}

// round 7
// speedup vs baseline: 3.0919x; 1.0409x over previous
#include <cuda_runtime.h>
#include <cuda_bf16.h>
#include <cstdint>
#include <math.h>

#define N_  4
#define C_  512
#define CT_ 512
#define L_  256
#define S_  4096
#define H_  16
#define D_  32

__device__ float g_K[(size_t)N_ * C_ * L_];
__device__ float g_V[(size_t)N_ * C_ * L_];

// ---------------- helpers ----------------
__device__ __forceinline__ float ex2f(float x) {
    float r; asm("ex2.approx.f32 %0, %1;" : "=f"(r) : "f"(x)); return r;
}
__device__ __forceinline__ uint32_t pack_bf2(float lo, float hi) {
    uint32_t r; asm("cvt.rn.bf16x2.f32 %0, %1, %2;" : "=r"(r) : "f"(hi), "f"(lo)); return r;
}
__device__ __forceinline__ float bf_lo(uint32_t r) { return __uint_as_float(r << 16); }
__device__ __forceinline__ float bf_hi(uint32_t r) { return __uint_as_float(r & 0xFFFF0000u); }
__device__ __forceinline__ void split2(float x0, float x1, uint32_t& hp, uint32_t& lp) {
    hp = pack_bf2(x0, x1);
    lp = pack_bf2(x0 - bf_lo(hp), x1 - bf_hi(hp));
}
__device__ __forceinline__ void mma16816(float* c, const uint32_t* a, uint32_t b0, uint32_t b1) {
    asm volatile("mma.sync.aligned.m16n8k16.row.col.f32.bf16.bf16.f32 "
                 "{%0,%1,%2,%3}, {%4,%5,%6,%7}, {%8,%9}, {%0,%1,%2,%3};"
                 : "+f"(c[0]), "+f"(c[1]), "+f"(c[2]), "+f"(c[3])
                 : "r"(a[0]), "r"(a[1]), "r"(a[2]), "r"(a[3]), "r"(b0), "r"(b1));
}
__device__ __forceinline__ void ldmx4(uint32_t* r, uint32_t addr) {
    asm volatile("ldmatrix.sync.aligned.m8n8.x4.shared.b16 {%0,%1,%2,%3}, [%4];"
                 : "=r"(r[0]), "=r"(r[1]), "=r"(r[2]), "=r"(r[3]) : "r"(addr));
}
__device__ __forceinline__ uint32_t smem_u32(const void* p) {
    uint32_t a;
    asm("{ .reg .u64 t; cvta.to.shared.u64 t, %1; cvt.u32.u64 %0, t; }" : "=r"(a) : "l"(p));
    return a;
}

// ---------------------------------------------------------------------------
// Kernel A: K/V projections (round-4 version, unchanged, proven)
// ---------------------------------------------------------------------------
extern "C" __global__ void __launch_bounds__(256)
proj_kv_kernel(const float* __restrict__ token,
               const float* __restrict__ Wv, const float* __restrict__ bv,
               const float* __restrict__ Wk, const float* __restrict__ bk)
{
    __shared__ float Wt[64][33];
    __shared__ float Tt[32][65];
    const int t  = threadIdx.x;
    const int tx = t & 15, ty = t >> 4;
    const int l0 = blockIdx.x * 64, o0 = blockIdx.y * 64;
    const int n = blockIdx.z >> 1, which = blockIdx.z & 1;
    const float* __restrict__ W    = which ? Wk : Wv;
    const float* __restrict__ bias = which ? bk : bv;
    float* out = which ? g_K : g_V;
    const float* tb = token + (size_t)n * CT_ * L_;

    float acc[4][4] = {};
    for (int kc = 0; kc < CT_; kc += 32) {
        #pragma unroll
        for (int i = t; i < 64 * 32; i += 256) {
            int o = i >> 5, c = i & 31;
            Wt[o][c] = W[(size_t)(o0 + o) * CT_ + kc + c];
        }
        #pragma unroll
        for (int i = t; i < 32 * 64; i += 256) {
            int c = i >> 6, l = i & 63;
            Tt[c][l] = tb[(size_t)(kc + c) * L_ + l0 + l];
        }
        __syncthreads();
        #pragma unroll 8
        for (int c = 0; c < 32; c++) {
            float a0 = Wt[ty*4+0][c], a1 = Wt[ty*4+1][c], a2 = Wt[ty*4+2][c], a3 = Wt[ty*4+3][c];
            float b0 = Tt[c][tx*4+0], b1 = Tt[c][tx*4+1], b2 = Tt[c][tx*4+2], b3 = Tt[c][tx*4+3];
            acc[0][0]+=a0*b0; acc[0][1]+=a0*b1; acc[0][2]+=a0*b2; acc[0][3]+=a0*b3;
            acc[1][0]+=a1*b0; acc[1][1]+=a1*b1; acc[1][2]+=a1*b2; acc[1][3]+=a1*b3;
            acc[2][0]+=a2*b0; acc[2][1]+=a2*b1; acc[2][2]+=a2*b2; acc[2][3]+=a2*b3;
            acc[3][0]+=a3*b0; acc[3][1]+=a3*b1; acc[3][2]+=a3*b2; acc[3][3]+=a3*b3;
        }
        __syncthreads();
    }
    #pragma unroll
    for (int i = 0; i < 4; i++) {
        int o = o0 + ty * 4 + i;
        float bb = bias[o];
        float4 v = make_float4(acc[i][0]+bb, acc[i][1]+bb, acc[i][2]+bb, acc[i][3]+bb);
        *(float4*)&out[((size_t)n * C_ + o) * L_ + l0 + tx * 4] = v;
    }
}

// ---------------------------------------------------------------------------
// Kernel B: mma.sync attention. Round-4 structure; mainloop fragments now via
// ldmatrix.x4 (K staged as [l][20] u32, V as [d][132] u32 — both conflict-free).
// ---------------------------------------------------------------------------
#define SB_F    0
#define SB_WQ   16896
#define SB_QHI  20992
#define SB_QLO  29696
#define SB_KHI  38400
#define SB_KLO  58880
#define SB_VHI  79360
#define SB_VLO  96256
#define SB_TOT  113152

extern "C" __global__ void __launch_bounds__(256, 2)
attn_mma_kernel(const float* __restrict__ feature,
                const float* __restrict__ Wq, const float* __restrict__ bq,
                float* __restrict__ dout)
{
    extern __shared__ char smem[];
    float*    smf = (float*)smem;
    uint32_t* QH  = (uint32_t*)(smem + SB_QHI);
    uint32_t* QL  = (uint32_t*)(smem + SB_QLO);
    uint32_t* KH  = (uint32_t*)(smem + SB_KHI);
    uint32_t* KL  = (uint32_t*)(smem + SB_KLO);
    uint32_t* VH  = (uint32_t*)(smem + SB_VHI);
    uint32_t* VL  = (uint32_t*)(smem + SB_VLO);
    float*    Osm = (float*)(smem + SB_QHI);      // reuse after barrier

    const int t    = threadIdx.x;
    const int lane = t & 31;
    const int wid  = t >> 5;
    const int g    = lane >> 2;
    const int tig  = lane & 3;
    const int s0 = blockIdx.x * 128;
    const int h  = blockIdx.y;
    const int n  = blockIdx.z;
    const uint32_t sb = smem_u32(smem);

    // ---------------- stage tiles (in-kernel bf16 split, round-4 style) ----
    const float* fb = feature + ((size_t)(n * C_ + h * D_)) * S_ + s0;
    #pragma unroll
    for (int i = t; i < 1024; i += 256) {                 // F: 32ch x 128s
        int row = i >> 5, c4 = (i & 31) << 2;
        *(float4*)&smf[row * 132 + c4] = *(const float4*)(fb + (size_t)row * S_ + c4);
    }
    #pragma unroll
    for (int i = t; i < 1024; i += 256)
        smf[SB_WQ/4 + i] = Wq[h * 1024 + i];

    const float* kb = g_K + ((size_t)(n * C_ + h * D_)) * L_;
    #pragma unroll 4
    for (int i = t; i < 4096; i += 256) {                 // K -> [l][20] u32
        int p = i >> 8, l = i & 255;
        float v0 = kb[(size_t)(2*p)   * L_ + l];
        float v1 = kb[(size_t)(2*p+1) * L_ + l];
        uint32_t hp, lp; split2(v0, v1, hp, lp);
        KH[l * 20 + p] = hp;
        KL[l * 20 + p] = lp;
    }
    const float* vb = g_V + ((size_t)(n * C_ + h * D_)) * L_;
    #pragma unroll 4
    for (int i = t; i < 4096; i += 256) {                 // V -> [d][132] u32
        int d = i >> 7, lp2 = i & 127;
        float2 v = *(const float2*)(vb + (size_t)d * L_ + lp2 * 2);
        uint32_t hp, lp; split2(v.x, v.y, hp, lp);
        VH[d * 132 + lp2] = hp;
        VL[d * 132 + lp2] = lp;
    }
    __syncthreads();

    // ---------------- Q projection -> bf16 split in smem ----------------
    {
        const int row = t & 127;
        const int d0  = (t >> 7) << 4;                    // 0 or 16
        float acc[16] = {};
        #pragma unroll 8
        for (int i = 0; i < 32; i++) {
            float f = smf[i * 132 + row];
            #pragma unroll
            for (int dd = 0; dd < 16; dd++)
                acc[dd] += smf[SB_WQ/4 + (d0 + dd) * 32 + i] * f;
        }
        const float scale = 0.2550354839f;                // (1/sqrt(32))*log2(e)
        #pragma unroll
        for (int j = 0; j < 8; j++) {
            int d = d0 + 2 * j;
            float q0 = (acc[2*j]   + bq[h*D_ + d])   * scale;
            float q1 = (acc[2*j+1] + bq[h*D_ + d+1]) * scale;
            uint32_t hp, lp; split2(q0, q1, hp, lp);
            QH[(d >> 1) * 136 + row] = hp;
            QL[(d >> 1) * 136 + row] = lp;
        }
    }
    __syncthreads();

    // ---------------- load Q A-fragments (then Q smem is dead) ----------
    const int r0 = wid * 16;
    uint32_t aH[2][4], aL[2][4];
    #pragma unroll
    for (int ks = 0; ks < 2; ks++) {
        int p0 = ks * 8 + tig;
        aH[ks][0] = QH[p0 * 136 + r0 + g];
        aH[ks][1] = QH[p0 * 136 + r0 + g + 8];
        aH[ks][2] = QH[(p0 + 4) * 136 + r0 + g];
        aH[ks][3] = QH[(p0 + 4) * 136 + r0 + g + 8];
        aL[ks][0] = QL[p0 * 136 + r0 + g];
        aL[ks][1] = QL[p0 * 136 + r0 + g + 8];
        aL[ks][2] = QL[(p0 + 4) * 136 + r0 + g];
        aL[ks][3] = QL[(p0 + 4) * 136 + r0 + g + 8];
    }
    __syncthreads();   // all warps done reading Q before O overwrites it

    // per-lane ldmatrix base addresses:
    // lanes 0-7: HI cols 0-3 | 8-15: HI cols 4-7 | 16-23: LO cols 0-3 | 24-31: LO cols 4-7
    const uint32_t kbase = sb + (lane < 16 ? SB_KHI : SB_KLO)
                         + ((uint32_t)(lane & 7) * 20 + ((uint32_t)((lane >> 3) & 1)) * 4) * 4;
    const uint32_t vbase = sb + (lane < 16 ? SB_VHI : SB_VLO)
                         + ((uint32_t)(lane & 7) * 132 + ((uint32_t)((lane >> 3) & 1)) * 4) * 4;

    // ---------------- fused scores -> exp -> PV loop --------------------
    float o[4][4] = {};
    float sum0 = 0.f, sum1 = 0.f;

    #pragma unroll 1
    for (int cb = 0; cb < 8; cb++) {
        // ---- GEMM1: 4 n-tiles of 8 cols, ldmatrix.x4 per (nt,ks) ----
        float c[4][4] = {};
        #pragma unroll
        for (int nt = 0; nt < 4; nt++) {
            const uint32_t ka = kbase + (uint32_t)(cb * 32 + nt * 8) * 80;
            #pragma unroll
            for (int ks = 0; ks < 2; ks++) {
                uint32_t b[4];
                ldmx4(b, ka + ks * 32);
                mma16816(c[nt], aH[ks], b[0], b[1]);
                mma16816(c[nt], aH[ks], b[2], b[3]);
                mma16816(c[nt], aL[ks], b[0], b[1]);
            }
        }
        // ---- exp + partial row sums ----
        float e[4][4];
        #pragma unroll
        for (int nt = 0; nt < 4; nt++) {
            e[nt][0] = ex2f(c[nt][0]);
            e[nt][1] = ex2f(c[nt][1]);
            e[nt][2] = ex2f(c[nt][2]);
            e[nt][3] = ex2f(c[nt][3]);
            sum0 += e[nt][0] + e[nt][1];
            sum1 += e[nt][2] + e[nt][3];
        }
        // ---- P fragments: C-frag pairs -> A-frag regs (register-only) ----
        uint32_t pH[2][4], pL[2][4];
        #pragma unroll
        for (int kc = 0; kc < 2; kc++) {
            int t0 = 2 * kc, t1 = 2 * kc + 1;
            split2(e[t0][0], e[t0][1], pH[kc][0], pL[kc][0]);
            split2(e[t0][2], e[t0][3], pH[kc][1], pL[kc][1]);
            split2(e[t1][0], e[t1][1], pH[kc][2], pL[kc][2]);
            split2(e[t1][2], e[t1][3], pH[kc][3], pL[kc][3]);
        }
        // ---- GEMM2: accumulate P @ V^T, ldmatrix.x4 per (dt,kc) ----
        #pragma unroll
        for (int dt = 0; dt < 4; dt++) {
            const uint32_t va = vbase + (uint32_t)dt * 4224 + (uint32_t)cb * 64;
            #pragma unroll
            for (int kc = 0; kc < 2; kc++) {
                uint32_t v[4];
                ldmx4(v, va + kc * 32);
                mma16816(o[dt], pH[kc], v[0], v[1]);
                mma16816(o[dt], pH[kc], v[2], v[3]);
                mma16816(o[dt], pL[kc], v[0], v[1]);
            }
        }
    }

    // ---------------- epilogue ----------------
    sum0 += __shfl_xor_sync(0xffffffffu, sum0, 1);
    sum0 += __shfl_xor_sync(0xffffffffu, sum0, 2);
    sum1 += __shfl_xor_sync(0xffffffffu, sum1, 1);
    sum1 += __shfl_xor_sync(0xffffffffu, sum1, 2);
    float rinv0 = __fdividef(1.0f, sum0);
    float rinv1 = __fdividef(1.0f, sum1);

    #pragma unroll
    for (int dt = 0; dt < 4; dt++) {
        int d = dt * 8 + 2 * tig;
        Osm[d * 132 + r0 + g]           = o[dt][0] * rinv0;
        Osm[(d + 1) * 132 + r0 + g]     = o[dt][1] * rinv0;
        Osm[d * 132 + r0 + g + 8]       = o[dt][2] * rinv1;
        Osm[(d + 1) * 132 + r0 + g + 8] = o[dt][3] * rinv1;
    }
    __syncthreads();

    float* ob = dout + ((size_t)(n * C_ + h * D_)) * S_ + s0;
    #pragma unroll
    for (int j = 0; j < 4; j++) {
        int i = t + j * 256;
        int d = i >> 5, c4 = (i & 31) << 2;
        float4 ov = *(float4*)&Osm[d * 132 + c4];
        float4 fv = *(float4*)&smf[d * 132 + c4];
        ov.x += fv.x; ov.y += fv.y; ov.z += fv.z; ov.w += fv.w;
        *(float4*)(ob + (size_t)d * S_ + c4) = ov;
    }
}

// ---------------------------------------------------------------------------
extern "C" void kernel_launch(void* const* d_in, const int* in_sizes, int n_in,
                              void* d_out, int out_size)
{
    const float* feature = (const float*)d_in[0];
    const float* token   = (const float*)d_in[1];
    const float* Wv      = (const float*)d_in[2];
    const float* bv      = (const float*)d_in[3];
    const float* Wk      = (const float*)d_in[4];
    const float* bk      = (const float*)d_in[5];
    const float* Wq      = (const float*)d_in[6];
    const float* bq      = (const float*)d_in[7];
    float* out = (float*)d_out;

    cudaFuncSetAttribute(attn_mma_kernel,
                         cudaFuncAttributeMaxDynamicSharedMemorySize, SB_TOT);

    proj_kv_kernel<<<dim3(L_/64, C_/64, N_*2), 256>>>(token, Wv, bv, Wk, bk);
    attn_mma_kernel<<<dim3(S_/128, H_, N_), 256, SB_TOT>>>(feature, Wq, bq, out);
}

// round 8
// speedup vs baseline: 3.3265x; 1.0759x over previous
#include <cuda_runtime.h>
#include <cuda_bf16.h>
#include <cstdint>
#include <math.h>

#define N_  4
#define C_  512
#define CT_ 512
#define L_  256
#define S_  4096
#define H_  16
#define D_  32

__device__ float g_K[(size_t)N_ * C_ * L_];
__device__ float g_V[(size_t)N_ * C_ * L_];

// ---------------- helpers ----------------
__device__ __forceinline__ float ex2f(float x) {
    float r; asm("ex2.approx.f32 %0, %1;" : "=f"(r) : "f"(x)); return r;
}
__device__ __forceinline__ uint32_t pack_bf2(float lo, float hi) {
    uint32_t r; asm("cvt.rn.bf16x2.f32 %0, %1, %2;" : "=r"(r) : "f"(hi), "f"(lo)); return r;
}
__device__ __forceinline__ float bf_lo(uint32_t r) { return __uint_as_float(r << 16); }
__device__ __forceinline__ float bf_hi(uint32_t r) { return __uint_as_float(r & 0xFFFF0000u); }
__device__ __forceinline__ void split2(float x0, float x1, uint32_t& hp, uint32_t& lp) {
    hp = pack_bf2(x0, x1);
    lp = pack_bf2(x0 - bf_lo(hp), x1 - bf_hi(hp));
}
__device__ __forceinline__ void mma16816(float* c, const uint32_t* a, uint32_t b0, uint32_t b1) {
    asm volatile("mma.sync.aligned.m16n8k16.row.col.f32.bf16.bf16.f32 "
                 "{%0,%1,%2,%3}, {%4,%5,%6,%7}, {%8,%9}, {%0,%1,%2,%3};"
                 : "+f"(c[0]), "+f"(c[1]), "+f"(c[2]), "+f"(c[3])
                 : "r"(a[0]), "r"(a[1]), "r"(a[2]), "r"(a[3]), "r"(b0), "r"(b1));
}
__device__ __forceinline__ void ldmx4(uint32_t* r, uint32_t addr) {
    asm volatile("ldmatrix.sync.aligned.m8n8.x4.shared.b16 {%0,%1,%2,%3}, [%4];"
                 : "=r"(r[0]), "=r"(r[1]), "=r"(r[2]), "=r"(r[3]) : "r"(addr));
}
__device__ __forceinline__ uint32_t smem_u32(const void* p) {
    uint32_t a;
    asm("{ .reg .u64 t; cvta.to.shared.u64 t, %1; cvt.u32.u64 %0, t; }" : "=r"(a) : "l"(p));
    return a;
}

// ---------------------------------------------------------------------------
// Kernel A: K/V projections (unchanged, proven)
// ---------------------------------------------------------------------------
extern "C" __global__ void __launch_bounds__(256)
proj_kv_kernel(const float* __restrict__ token,
               const float* __restrict__ Wv, const float* __restrict__ bv,
               const float* __restrict__ Wk, const float* __restrict__ bk)
{
    __shared__ float Wt[64][33];
    __shared__ float Tt[32][65];
    const int t  = threadIdx.x;
    const int tx = t & 15, ty = t >> 4;
    const int l0 = blockIdx.x * 64, o0 = blockIdx.y * 64;
    const int n = blockIdx.z >> 1, which = blockIdx.z & 1;
    const float* __restrict__ W    = which ? Wk : Wv;
    const float* __restrict__ bias = which ? bk : bv;
    float* out = which ? g_K : g_V;
    const float* tb = token + (size_t)n * CT_ * L_;

    float acc[4][4] = {};
    for (int kc = 0; kc < CT_; kc += 32) {
        #pragma unroll
        for (int i = t; i < 64 * 32; i += 256) {
            int o = i >> 5, c = i & 31;
            Wt[o][c] = W[(size_t)(o0 + o) * CT_ + kc + c];
        }
        #pragma unroll
        for (int i = t; i < 32 * 64; i += 256) {
            int c = i >> 6, l = i & 63;
            Tt[c][l] = tb[(size_t)(kc + c) * L_ + l0 + l];
        }
        __syncthreads();
        #pragma unroll 8
        for (int c = 0; c < 32; c++) {
            float a0 = Wt[ty*4+0][c], a1 = Wt[ty*4+1][c], a2 = Wt[ty*4+2][c], a3 = Wt[ty*4+3][c];
            float b0 = Tt[c][tx*4+0], b1 = Tt[c][tx*4+1], b2 = Tt[c][tx*4+2], b3 = Tt[c][tx*4+3];
            acc[0][0]+=a0*b0; acc[0][1]+=a0*b1; acc[0][2]+=a0*b2; acc[0][3]+=a0*b3;
            acc[1][0]+=a1*b0; acc[1][1]+=a1*b1; acc[1][2]+=a1*b2; acc[1][3]+=a1*b3;
            acc[2][0]+=a2*b0; acc[2][1]+=a2*b1; acc[2][2]+=a2*b2; acc[2][3]+=a2*b3;
            acc[3][0]+=a3*b0; acc[3][1]+=a3*b1; acc[3][2]+=a3*b2; acc[3][3]+=a3*b3;
        }
        __syncthreads();
    }
    #pragma unroll
    for (int i = 0; i < 4; i++) {
        int o = o0 + ty * 4 + i;
        float bb = bias[o];
        float4 v = make_float4(acc[i][0]+bb, acc[i][1]+bb, acc[i][2]+bb, acc[i][3]+bb);
        *(float4*)&out[((size_t)n * C_ + o) * L_ + l0 + tx * 4] = v;
    }
}

// ---------------------------------------------------------------------------
// Kernel B: mma.sync attention, 2-pass GEMM1 (Qhi·Khi + Qhi·Klo), 2-pass GEMM2
// (Phi·Vhi + Phi·Vlo). O tile reuses the dead F region; residual re-read from
// global at epilogue.
// ---------------------------------------------------------------------------
#define SB_F    0          // 32x132 f32 (F; Osm after mainloop)
#define SB_WQ   16896      // 1024 f32
#define SB_QHI  20992      // 16x136 u32
#define SB_KHI  29696      // 256x20 u32
#define SB_KLO  50176
#define SB_VHI  70656      // 32x132 u32
#define SB_VLO  87552
#define SB_TOT  104448

extern "C" __global__ void __launch_bounds__(256, 2)
attn_mma_kernel(const float* __restrict__ feature,
                const float* __restrict__ Wq, const float* __restrict__ bq,
                float* __restrict__ dout)
{
    extern __shared__ char smem[];
    float*    smf = (float*)smem;
    uint32_t* QH  = (uint32_t*)(smem + SB_QHI);
    uint32_t* KH  = (uint32_t*)(smem + SB_KHI);
    uint32_t* KL  = (uint32_t*)(smem + SB_KLO);
    uint32_t* VH  = (uint32_t*)(smem + SB_VHI);
    uint32_t* VL  = (uint32_t*)(smem + SB_VLO);
    float*    Osm = (float*)smem;                 // reuse F region after mainloop

    const int t    = threadIdx.x;
    const int lane = t & 31;
    const int wid  = t >> 5;
    const int g    = lane >> 2;
    const int tig  = lane & 3;
    const int s0 = blockIdx.x * 128;
    const int h  = blockIdx.y;
    const int n  = blockIdx.z;
    const uint32_t sb = smem_u32(smem);

    // ---------------- stage tiles ----------------
    const float* fb = feature + ((size_t)(n * C_ + h * D_)) * S_ + s0;
    #pragma unroll
    for (int i = t; i < 1024; i += 256) {                 // F: 32ch x 128s
        int row = i >> 5, c4 = (i & 31) << 2;
        *(float4*)&smf[row * 132 + c4] = *(const float4*)(fb + (size_t)row * S_ + c4);
    }
    #pragma unroll
    for (int i = t; i < 1024; i += 256)
        smf[SB_WQ/4 + i] = Wq[h * 1024 + i];

    const float* kb = g_K + ((size_t)(n * C_ + h * D_)) * L_;
    #pragma unroll 4
    for (int i = t; i < 4096; i += 256) {                 // K -> [l][20] u32
        int p = i >> 8, l = i & 255;
        float v0 = kb[(size_t)(2*p)   * L_ + l];
        float v1 = kb[(size_t)(2*p+1) * L_ + l];
        uint32_t hp, lp; split2(v0, v1, hp, lp);
        KH[l * 20 + p] = hp;
        KL[l * 20 + p] = lp;
    }
    const float* vb = g_V + ((size_t)(n * C_ + h * D_)) * L_;
    #pragma unroll 4
    for (int i = t; i < 4096; i += 256) {                 // V -> [d][132] u32
        int d = i >> 7, lp2 = i & 127;
        float2 v = *(const float2*)(vb + (size_t)d * L_ + lp2 * 2);
        uint32_t hp, lp; split2(v.x, v.y, hp, lp);
        VH[d * 132 + lp2] = hp;
        VL[d * 132 + lp2] = lp;
    }
    __syncthreads();

    // ---------------- Q projection -> bf16 (hi only) in smem ----------------
    {
        const int row = t & 127;
        const int d0  = (t >> 7) << 4;                    // 0 or 16
        float acc[16] = {};
        #pragma unroll 8
        for (int i = 0; i < 32; i++) {
            float f = smf[i * 132 + row];
            #pragma unroll
            for (int dd = 0; dd < 16; dd++)
                acc[dd] += smf[SB_WQ/4 + (d0 + dd) * 32 + i] * f;
        }
        const float scale = 0.2550354839f;                // (1/sqrt(32))*log2(e)
        #pragma unroll
        for (int j = 0; j < 8; j++) {
            int d = d0 + 2 * j;
            float q0 = (acc[2*j]   + bq[h*D_ + d])   * scale;
            float q1 = (acc[2*j+1] + bq[h*D_ + d+1]) * scale;
            QH[(d >> 1) * 136 + row] = pack_bf2(q0, q1);
        }
    }
    __syncthreads();

    // ---------------- load Q A-fragments ----------
    const int r0 = wid * 16;
    uint32_t aH[2][4];
    #pragma unroll
    for (int ks = 0; ks < 2; ks++) {
        int p0 = ks * 8 + tig;
        aH[ks][0] = QH[p0 * 136 + r0 + g];
        aH[ks][1] = QH[p0 * 136 + r0 + g + 8];
        aH[ks][2] = QH[(p0 + 4) * 136 + r0 + g];
        aH[ks][3] = QH[(p0 + 4) * 136 + r0 + g + 8];
    }
    __syncthreads();   // all warps done before Osm overwrites F later

    // per-lane ldmatrix base addresses (hi for lanes 0-15, lo for 16-31)
    const uint32_t kbase = sb + (lane < 16 ? SB_KHI : SB_KLO)
                         + ((uint32_t)(lane & 7) * 20 + ((uint32_t)((lane >> 3) & 1)) * 4) * 4;
    const uint32_t vbase = sb + (lane < 16 ? SB_VHI : SB_VLO)
                         + ((uint32_t)(lane & 7) * 132 + ((uint32_t)((lane >> 3) & 1)) * 4) * 4;

    // ---------------- fused scores -> exp -> PV loop --------------------
    float o[4][4] = {};
    float sum0 = 0.f, sum1 = 0.f;

    #pragma unroll 1
    for (int cb = 0; cb < 8; cb++) {
        // ---- GEMM1: scores = Qhi·Khi + Qhi·Klo ----
        float c[4][4] = {};
        #pragma unroll
        for (int nt = 0; nt < 4; nt++) {
            const uint32_t ka = kbase + (uint32_t)(cb * 32 + nt * 8) * 80;
            #pragma unroll
            for (int ks = 0; ks < 2; ks++) {
                uint32_t b[4];
                ldmx4(b, ka + ks * 32);
                mma16816(c[nt], aH[ks], b[0], b[1]);   // hi·hi
                mma16816(c[nt], aH[ks], b[2], b[3]);   // hi·lo
            }
        }
        // ---- exp + partial row sums ----
        float e[4][4];
        #pragma unroll
        for (int nt = 0; nt < 4; nt++) {
            e[nt][0] = ex2f(c[nt][0]);
            e[nt][1] = ex2f(c[nt][1]);
            e[nt][2] = ex2f(c[nt][2]);
            e[nt][3] = ex2f(c[nt][3]);
            sum0 += e[nt][0] + e[nt][1];
            sum1 += e[nt][2] + e[nt][3];
        }
        // ---- P -> bf16 (hi only), register-to-register ----
        uint32_t pH[2][4];
        #pragma unroll
        for (int kc = 0; kc < 2; kc++) {
            int t0 = 2 * kc, t1 = 2 * kc + 1;
            pH[kc][0] = pack_bf2(e[t0][0], e[t0][1]);
            pH[kc][1] = pack_bf2(e[t0][2], e[t0][3]);
            pH[kc][2] = pack_bf2(e[t1][0], e[t1][1]);
            pH[kc][3] = pack_bf2(e[t1][2], e[t1][3]);
        }
        // ---- GEMM2: out += Phi·Vhi + Phi·Vlo ----
        #pragma unroll
        for (int dt = 0; dt < 4; dt++) {
            const uint32_t va = vbase + (uint32_t)dt * 4224 + (uint32_t)cb * 64;
            #pragma unroll
            for (int kc = 0; kc < 2; kc++) {
                uint32_t v[4];
                ldmx4(v, va + kc * 32);
                mma16816(o[dt], pH[kc], v[0], v[1]);   // P·Vhi
                mma16816(o[dt], pH[kc], v[2], v[3]);   // P·Vlo
            }
        }
    }

    // ---------------- epilogue ----------------
    sum0 += __shfl_xor_sync(0xffffffffu, sum0, 1);
    sum0 += __shfl_xor_sync(0xffffffffu, sum0, 2);
    sum1 += __shfl_xor_sync(0xffffffffu, sum1, 1);
    sum1 += __shfl_xor_sync(0xffffffffu, sum1, 2);
    float rinv0 = __fdividef(1.0f, sum0);
    float rinv1 = __fdividef(1.0f, sum1);

    __syncthreads();   // everyone past F reads (long past), safe to overwrite
    #pragma unroll
    for (int dt = 0; dt < 4; dt++) {
        int d = dt * 8 + 2 * tig;
        Osm[d * 132 + r0 + g]           = o[dt][0] * rinv0;
        Osm[(d + 1) * 132 + r0 + g]     = o[dt][1] * rinv0;
        Osm[d * 132 + r0 + g + 8]       = o[dt][2] * rinv1;
        Osm[(d + 1) * 132 + r0 + g + 8] = o[dt][3] * rinv1;
    }
    __syncthreads();

    float* ob = dout + ((size_t)(n * C_ + h * D_)) * S_ + s0;
    #pragma unroll
    for (int j = 0; j < 4; j++) {
        int i = t + j * 256;
        int d = i >> 5, c4 = (i & 31) << 2;
        float4 ov = *(float4*)&Osm[d * 132 + c4];
        float4 fv = *(const float4*)(fb + (size_t)d * S_ + c4);   // residual from global (L2)
        ov.x += fv.x; ov.y += fv.y; ov.z += fv.z; ov.w += fv.w;
        *(float4*)(ob + (size_t)d * S_ + c4) = ov;
    }
}

// ---------------------------------------------------------------------------
extern "C" void kernel_launch(void* const* d_in, const int* in_sizes, int n_in,
                              void* d_out, int out_size)
{
    const float* feature = (const float*)d_in[0];
    const float* token   = (const float*)d_in[1];
    const float* Wv      = (const float*)d_in[2];
    const float* bv      = (const float*)d_in[3];
    const float* Wk      = (const float*)d_in[4];
    const float* bk      = (const float*)d_in[5];
    const float* Wq      = (const float*)d_in[6];
    const float* bq      = (const float*)d_in[7];
    float* out = (float*)d_out;

    cudaFuncSetAttribute(attn_mma_kernel,
                         cudaFuncAttributeMaxDynamicSharedMemorySize, SB_TOT);

    proj_kv_kernel<<<dim3(L_/64, C_/64, N_*2), 256>>>(token, Wv, bv, Wk, bk);
    attn_mma_kernel<<<dim3(S_/128, H_, N_), 256, SB_TOT>>>(feature, Wq, bq, out);
}

// round 11
// speedup vs baseline: 3.5416x; 1.0647x over previous
#include <cuda_runtime.h>
#include <cuda_bf16.h>
#include <cstdint>
#include <math.h>

#define N_  4
#define C_  512
#define CT_ 512
#define L_  256
#define S_  4096
#define H_  16
#define D_  32

__device__ float g_K[(size_t)N_ * C_ * L_];
__device__ float g_V[(size_t)N_ * C_ * L_];

// ---------------- helpers ----------------
__device__ __forceinline__ float ex2f(float x) {
    float r; asm("ex2.approx.f32 %0, %1;" : "=f"(r) : "f"(x)); return r;
}
__device__ __forceinline__ uint32_t pack_bf2(float lo, float hi) {
    uint32_t r; asm("cvt.rn.bf16x2.f32 %0, %1, %2;" : "=r"(r) : "f"(hi), "f"(lo)); return r;
}
__device__ __forceinline__ float bf_lo(uint32_t r) { return __uint_as_float(r << 16); }
__device__ __forceinline__ float bf_hi(uint32_t r) { return __uint_as_float(r & 0xFFFF0000u); }
__device__ __forceinline__ void split2(float x0, float x1, uint32_t& hp, uint32_t& lp) {
    hp = pack_bf2(x0, x1);
    lp = pack_bf2(x0 - bf_lo(hp), x1 - bf_hi(hp));
}
__device__ __forceinline__ void mma16816(float* c, const uint32_t* a, uint32_t b0, uint32_t b1) {
    asm volatile("mma.sync.aligned.m16n8k16.row.col.f32.bf16.bf16.f32 "
                 "{%0,%1,%2,%3}, {%4,%5,%6,%7}, {%8,%9}, {%0,%1,%2,%3};"
                 : "+f"(c[0]), "+f"(c[1]), "+f"(c[2]), "+f"(c[3])
                 : "r"(a[0]), "r"(a[1]), "r"(a[2]), "r"(a[3]), "r"(b0), "r"(b1));
}
__device__ __forceinline__ void ldmx4(uint32_t* r, uint32_t addr) {
    asm volatile("ldmatrix.sync.aligned.m8n8.x4.shared.b16 {%0,%1,%2,%3}, [%4];"
                 : "=r"(r[0]), "=r"(r[1]), "=r"(r[2]), "=r"(r[3]) : "r"(addr));
}
__device__ __forceinline__ uint32_t smem_u32(const void* p) {
    uint32_t a;
    asm("{ .reg .u64 t; cvta.to.shared.u64 t, %1; cvt.u32.u64 %0, t; }" : "=r"(a) : "l"(p));
    return a;
}

// ---------------------------------------------------------------------------
// Kernel A: K/V projection as bf16-split mma GEMM (3-pass).
// Block tile: M=128 (out channels), N=128 (l), K=512 (ct) in chunks of 32.
// grid = (L/128=2, C/128=4, N*2=8) -> 64 blocks, 256 threads (8 warps).
// Output: plain fp32 g_K/g_V, same layout round 8's attn expects.
// ---------------------------------------------------------------------------
#define PJ_ASH  0
#define PJ_ASL  8704
#define PJ_BSH  17408
#define PJ_BSL  27648
#define PJ_TOT  67584

extern "C" __global__ void __launch_bounds__(256, 1)
proj_mma_kernel(const float* __restrict__ token,
                const float* __restrict__ Wv, const float* __restrict__ bv,
                const float* __restrict__ Wk, const float* __restrict__ bk)
{
    extern __shared__ char smem[];
    uint32_t* ASH = (uint32_t*)(smem + PJ_ASH);
    uint32_t* ASL = (uint32_t*)(smem + PJ_ASL);
    uint32_t* BSH = (uint32_t*)(smem + PJ_BSH);
    uint32_t* BSL = (uint32_t*)(smem + PJ_BSL);
    float*    Csm = (float*)smem;
    const uint32_t sb = smem_u32(smem);

    const int t    = threadIdx.x;
    const int lane = t & 31;
    const int wid  = t >> 5;
    const int g    = lane >> 2;
    const int tig  = lane & 3;
    const int l0 = blockIdx.x * 128;
    const int o0 = blockIdx.y * 128;
    const int n = blockIdx.z >> 1, which = blockIdx.z & 1;   // 0 -> V, 1 -> K
    const float* __restrict__ W    = which ? Wk : Wv;
    const float* __restrict__ bias = which ? bk : bv;
    float* out = which ? g_K : g_V;
    const float* tb = token + (size_t)n * CT_ * L_;

    const uint32_t kbase = sb + (lane < 16 ? PJ_BSH : PJ_BSL)
                         + ((uint32_t)(lane & 7) * 20 + ((uint32_t)((lane >> 3) & 1)) * 4) * 4;
    const int r0 = wid * 16;

    float c[16][4] = {};

    for (int kc = 0; kc < CT_; kc += 32) {
        __syncthreads();
        // stage A: W[o0+row][kc+2cp .. +1] -> ASH/ASL[cp][row]
        #pragma unroll
        for (int i = t; i < 2048; i += 256) {
            int row = i >> 4, cp = i & 15;
            float2 w = *(const float2*)(W + (size_t)(o0 + row) * CT_ + kc + 2 * cp);
            uint32_t hp, lp; split2(w.x, w.y, hp, lp);
            ASH[cp * 136 + row] = hp;
            ASL[cp * 136 + row] = lp;
        }
        // stage B: token[kc+2cp..][l0+l] -> BSH/BSL[l][cp]
        #pragma unroll
        for (int i = t; i < 2048; i += 256) {
            int cp = i >> 7, l = i & 127;
            float t0 = tb[(size_t)(kc + 2 * cp) * L_ + l0 + l];
            float t1 = tb[(size_t)(kc + 2 * cp + 1) * L_ + l0 + l];
            uint32_t hp, lp; split2(t0, t1, hp, lp);
            BSH[l * 20 + cp] = hp;
            BSL[l * 20 + cp] = lp;
        }
        __syncthreads();

        uint32_t aH[2][4], aL[2][4];
        #pragma unroll
        for (int ks = 0; ks < 2; ks++) {
            int p0 = ks * 8 + tig;
            aH[ks][0] = ASH[p0 * 136 + r0 + g];
            aH[ks][1] = ASH[p0 * 136 + r0 + g + 8];
            aH[ks][2] = ASH[(p0 + 4) * 136 + r0 + g];
            aH[ks][3] = ASH[(p0 + 4) * 136 + r0 + g + 8];
            aL[ks][0] = ASL[p0 * 136 + r0 + g];
            aL[ks][1] = ASL[p0 * 136 + r0 + g + 8];
            aL[ks][2] = ASL[(p0 + 4) * 136 + r0 + g];
            aL[ks][3] = ASL[(p0 + 4) * 136 + r0 + g + 8];
        }
        #pragma unroll
        for (int nt = 0; nt < 16; nt++) {
            const uint32_t ka = kbase + (uint32_t)nt * 640;
            #pragma unroll
            for (int ks = 0; ks < 2; ks++) {
                uint32_t b[4];
                ldmx4(b, ka + ks * 32);
                mma16816(c[nt], aH[ks], b[0], b[1]);   // hi*hi
                mma16816(c[nt], aH[ks], b[2], b[3]);   // hi*lo
                mma16816(c[nt], aL[ks], b[0], b[1]);   // lo*hi
            }
        }
    }
    __syncthreads();

    // dump C to smem [row=channel 128][col=l 132-stride]
    #pragma unroll
    for (int nt = 0; nt < 16; nt++) {
        int col = nt * 8 + 2 * tig;
        Csm[(r0 + g) * 132 + col]           = c[nt][0];
        Csm[(r0 + g) * 132 + col + 1]       = c[nt][1];
        Csm[(r0 + g + 8) * 132 + col]       = c[nt][2];
        Csm[(r0 + g + 8) * 132 + col + 1]   = c[nt][3];
    }
    __syncthreads();

    // epilogue: bias add + fp32 store to g_K/g_V (round-8 layout)
    #pragma unroll
    for (int i = t; i < 4096; i += 256) {
        int row = i >> 5, c4 = (i & 31) << 2;
        float bb = bias[o0 + row];
        float4 v = *(float4*)&Csm[row * 132 + c4];
        v.x += bb; v.y += bb; v.z += bb; v.w += bb;
        *(float4*)&out[((size_t)n * C_ + o0 + row) * L_ + l0 + c4] = v;
    }
}

// ---------------------------------------------------------------------------
// Kernel B: mma.sync attention — BYTE-IDENTICAL to round 8 (passed, 102.8us)
// ---------------------------------------------------------------------------
#define SB_F    0          // 32x132 f32 (F; Osm after mainloop)
#define SB_WQ   16896      // 1024 f32
#define SB_QHI  20992      // 16x136 u32
#define SB_KHI  29696      // 256x20 u32
#define SB_KLO  50176
#define SB_VHI  70656      // 32x132 u32
#define SB_VLO  87552
#define SB_TOT  104448

extern "C" __global__ void __launch_bounds__(256, 2)
attn_mma_kernel(const float* __restrict__ feature,
                const float* __restrict__ Wq, const float* __restrict__ bq,
                float* __restrict__ dout)
{
    extern __shared__ char smem[];
    float*    smf = (float*)smem;
    uint32_t* QH  = (uint32_t*)(smem + SB_QHI);
    uint32_t* KH  = (uint32_t*)(smem + SB_KHI);
    uint32_t* KL  = (uint32_t*)(smem + SB_KLO);
    uint32_t* VH  = (uint32_t*)(smem + SB_VHI);
    uint32_t* VL  = (uint32_t*)(smem + SB_VLO);
    float*    Osm = (float*)smem;

    const int t    = threadIdx.x;
    const int lane = t & 31;
    const int wid  = t >> 5;
    const int g    = lane >> 2;
    const int tig  = lane & 3;
    const int s0 = blockIdx.x * 128;
    const int h  = blockIdx.y;
    const int n  = blockIdx.z;
    const uint32_t sb = smem_u32(smem);

    const float* fb = feature + ((size_t)(n * C_ + h * D_)) * S_ + s0;
    #pragma unroll
    for (int i = t; i < 1024; i += 256) {
        int row = i >> 5, c4 = (i & 31) << 2;
        *(float4*)&smf[row * 132 + c4] = *(const float4*)(fb + (size_t)row * S_ + c4);
    }
    #pragma unroll
    for (int i = t; i < 1024; i += 256)
        smf[SB_WQ/4 + i] = Wq[h * 1024 + i];

    const float* kb = g_K + ((size_t)(n * C_ + h * D_)) * L_;
    #pragma unroll 4
    for (int i = t; i < 4096; i += 256) {
        int p = i >> 8, l = i & 255;
        float v0 = kb[(size_t)(2*p)   * L_ + l];
        float v1 = kb[(size_t)(2*p+1) * L_ + l];
        uint32_t hp, lp; split2(v0, v1, hp, lp);
        KH[l * 20 + p] = hp;
        KL[l * 20 + p] = lp;
    }
    const float* vb = g_V + ((size_t)(n * C_ + h * D_)) * L_;
    #pragma unroll 4
    for (int i = t; i < 4096; i += 256) {
        int d = i >> 7, lp2 = i & 127;
        float2 v = *(const float2*)(vb + (size_t)d * L_ + lp2 * 2);
        uint32_t hp, lp; split2(v.x, v.y, hp, lp);
        VH[d * 132 + lp2] = hp;
        VL[d * 132 + lp2] = lp;
    }
    __syncthreads();

    {
        const int row = t & 127;
        const int d0  = (t >> 7) << 4;
        float acc[16] = {};
        #pragma unroll 8
        for (int i = 0; i < 32; i++) {
            float f = smf[i * 132 + row];
            #pragma unroll
            for (int dd = 0; dd < 16; dd++)
                acc[dd] += smf[SB_WQ/4 + (d0 + dd) * 32 + i] * f;
        }
        const float scale = 0.2550354839f;
        #pragma unroll
        for (int j = 0; j < 8; j++) {
            int d = d0 + 2 * j;
            float q0 = (acc[2*j]   + bq[h*D_ + d])   * scale;
            float q1 = (acc[2*j+1] + bq[h*D_ + d+1]) * scale;
            QH[(d >> 1) * 136 + row] = pack_bf2(q0, q1);
        }
    }
    __syncthreads();

    const int r0 = wid * 16;
    uint32_t aH[2][4];
    #pragma unroll
    for (int ks = 0; ks < 2; ks++) {
        int p0 = ks * 8 + tig;
        aH[ks][0] = QH[p0 * 136 + r0 + g];
        aH[ks][1] = QH[p0 * 136 + r0 + g + 8];
        aH[ks][2] = QH[(p0 + 4) * 136 + r0 + g];
        aH[ks][3] = QH[(p0 + 4) * 136 + r0 + g + 8];
    }
    __syncthreads();

    const uint32_t kbase = sb + (lane < 16 ? SB_KHI : SB_KLO)
                         + ((uint32_t)(lane & 7) * 20 + ((uint32_t)((lane >> 3) & 1)) * 4) * 4;
    const uint32_t vbase = sb + (lane < 16 ? SB_VHI : SB_VLO)
                         + ((uint32_t)(lane & 7) * 132 + ((uint32_t)((lane >> 3) & 1)) * 4) * 4;

    float o[4][4] = {};
    float sum0 = 0.f, sum1 = 0.f;

    #pragma unroll 1
    for (int cb = 0; cb < 8; cb++) {
        float c[4][4] = {};
        #pragma unroll
        for (int nt = 0; nt < 4; nt++) {
            const uint32_t ka = kbase + (uint32_t)(cb * 32 + nt * 8) * 80;
            #pragma unroll
            for (int ks = 0; ks < 2; ks++) {
                uint32_t b[4];
                ldmx4(b, ka + ks * 32);
                mma16816(c[nt], aH[ks], b[0], b[1]);
                mma16816(c[nt], aH[ks], b[2], b[3]);
            }
        }
        float e[4][4];
        #pragma unroll
        for (int nt = 0; nt < 4; nt++) {
            e[nt][0] = ex2f(c[nt][0]);
            e[nt][1] = ex2f(c[nt][1]);
            e[nt][2] = ex2f(c[nt][2]);
            e[nt][3] = ex2f(c[nt][3]);
            sum0 += e[nt][0] + e[nt][1];
            sum1 += e[nt][2] + e[nt][3];
        }
        uint32_t pH[2][4];
        #pragma unroll
        for (int kc = 0; kc < 2; kc++) {
            int t0 = 2 * kc, t1 = 2 * kc + 1;
            pH[kc][0] = pack_bf2(e[t0][0], e[t0][1]);
            pH[kc][1] = pack_bf2(e[t0][2], e[t0][3]);
            pH[kc][2] = pack_bf2(e[t1][0], e[t1][1]);
            pH[kc][3] = pack_bf2(e[t1][2], e[t1][3]);
        }
        #pragma unroll
        for (int dt = 0; dt < 4; dt++) {
            const uint32_t va = vbase + (uint32_t)dt * 4224 + (uint32_t)cb * 64;
            #pragma unroll
            for (int kc = 0; kc < 2; kc++) {
                uint32_t v[4];
                ldmx4(v, va + kc * 32);
                mma16816(o[dt], pH[kc], v[0], v[1]);
                mma16816(o[dt], pH[kc], v[2], v[3]);
            }
        }
    }

    sum0 += __shfl_xor_sync(0xffffffffu, sum0, 1);
    sum0 += __shfl_xor_sync(0xffffffffu, sum0, 2);
    sum1 += __shfl_xor_sync(0xffffffffu, sum1, 1);
    sum1 += __shfl_xor_sync(0xffffffffu, sum1, 2);
    float rinv0 = __fdividef(1.0f, sum0);
    float rinv1 = __fdividef(1.0f, sum1);

    __syncthreads();
    #pragma unroll
    for (int dt = 0; dt < 4; dt++) {
        int d = dt * 8 + 2 * tig;
        Osm[d * 132 + r0 + g]           = o[dt][0] * rinv0;
        Osm[(d + 1) * 132 + r0 + g]     = o[dt][1] * rinv0;
        Osm[d * 132 + r0 + g + 8]       = o[dt][2] * rinv1;
        Osm[(d + 1) * 132 + r0 + g + 8] = o[dt][3] * rinv1;
    }
    __syncthreads();

    float* ob = dout + ((size_t)(n * C_ + h * D_)) * S_ + s0;
    #pragma unroll
    for (int j = 0; j < 4; j++) {
        int i = t + j * 256;
        int d = i >> 5, c4 = (i & 31) << 2;
        float4 ov = *(float4*)&Osm[d * 132 + c4];
        float4 fv = *(const float4*)(fb + (size_t)d * S_ + c4);
        ov.x += fv.x; ov.y += fv.y; ov.z += fv.z; ov.w += fv.w;
        *(float4*)(ob + (size_t)d * S_ + c4) = ov;
    }
}

// ---------------------------------------------------------------------------
extern "C" void kernel_launch(void* const* d_in, const int* in_sizes, int n_in,
                              void* d_out, int out_size)
{
    const float* feature = (const float*)d_in[0];
    const float* token   = (const float*)d_in[1];
    const float* Wv      = (const float*)d_in[2];
    const float* bv      = (const float*)d_in[3];
    const float* Wk      = (const float*)d_in[4];
    const float* bk      = (const float*)d_in[5];
    const float* Wq      = (const float*)d_in[6];
    const float* bq      = (const float*)d_in[7];
    float* out = (float*)d_out;

    cudaFuncSetAttribute(proj_mma_kernel,
                         cudaFuncAttributeMaxDynamicSharedMemorySize, PJ_TOT);
    cudaFuncSetAttribute(attn_mma_kernel,
                         cudaFuncAttributeMaxDynamicSharedMemorySize, SB_TOT);

    proj_mma_kernel<<<dim3(L_/128, C_/128, N_*2), 256, PJ_TOT>>>(token, Wv, bv, Wk, bk);
    attn_mma_kernel<<<dim3(S_/128, H_, N_), 256, SB_TOT>>>(feature, Wq, bq, out);
}